// round 2
// baseline (speedup 1.0000x reference)
#include <cuda_runtime.h>
#include <math.h>

#define N_NODES   50000
#define N_EDGES   800000
#define IN_DIM    128
#define OUT_DIM   64
#define NEG_SLOPE 0.01f

// ---------------- scratch (static device globals; no allocation) ------------
__device__ float g_z[N_NODES * OUT_DIM];   // z = h @ fc_w^T
__device__ float g_s[N_NODES];             // z[n] . a_src
__device__ float g_d[N_NODES];             // z[n] . a_dst
__device__ int   g_rs[N_NODES + 1];        // row_start per dst node (dst is sorted)

// ---------------------------------------------------------------------------
// K1: z = h @ fc_w^T   (M=50000, N=64, K=128), fp32, K chunked by 32.
// Block: 256 threads, 64-node tile, 4x4 register tile per thread.
// smem: ws chunk 32x64 (8 KB) + hs chunk 64x36 (9 KB) = 17 KB.
// ---------------------------------------------------------------------------
#define BM 64
#define BK 32
#define HSW (BK + 4)   // 36 floats/row; 36*4=144 B, 16B-aligned for float4

__global__ __launch_bounds__(256) void gemm_kernel(const float* __restrict__ h,
                                                   const float* __restrict__ fw) {
    __shared__ float ws[BK * OUT_DIM];  // ws[kk*64 + o]
    __shared__ float hs[BM * HSW];      // hs[n*HSW + kk]

    const int t = threadIdx.x;
    const int node0 = blockIdx.x * BM;

    const int tx = t & 15;   // out group: outs tx*4..tx*4+3
    const int ty = t >> 4;   // node group: nodes ty*4..ty*4+3

    float acc[4][4];
#pragma unroll
    for (int r = 0; r < 4; r++)
#pragma unroll
        for (int c = 0; c < 4; c++) acc[r][c] = 0.f;

    for (int kb = 0; kb < IN_DIM; kb += BK) {
        // load weight chunk (transposed to k-major): fw[o*128 + kb + kk]
        for (int i = t; i < BK * OUT_DIM; i += 256) {
            int o  = i >> 5;        // 0..63
            int kk = i & (BK - 1);  // 0..31
            ws[kk * OUT_DIM + o] = fw[o * IN_DIM + kb + kk];
        }
        // load h chunk (float4, guarded on last partial block)
        for (int i = t; i < BM * (BK / 4); i += 256) {
            int n  = i / (BK / 4);
            int kq = i % (BK / 4);
            int gn = node0 + n;
            float4 v = make_float4(0.f, 0.f, 0.f, 0.f);
            if (gn < N_NODES)
                v = ((const float4*)(h + (size_t)gn * IN_DIM + kb))[kq];
            *((float4*)&hs[n * HSW + kq * 4]) = v;
        }
        __syncthreads();

#pragma unroll
        for (int k = 0; k < BK; k++) {
            float wv[4], hv[4];
#pragma unroll
            for (int c = 0; c < 4; c++) wv[c] = ws[k * OUT_DIM + tx * 4 + c];
#pragma unroll
            for (int r = 0; r < 4; r++) hv[r] = hs[(ty * 4 + r) * HSW + k];
#pragma unroll
            for (int r = 0; r < 4; r++)
#pragma unroll
                for (int c = 0; c < 4; c++) acc[r][c] += hv[r] * wv[c];
        }
        __syncthreads();
    }

#pragma unroll
    for (int r = 0; r < 4; r++) {
        int gn = node0 + ty * 4 + r;
        if (gn < N_NODES) {
            float4 v = make_float4(acc[r][0], acc[r][1], acc[r][2], acc[r][3]);
            *((float4*)&g_z[(size_t)gn * OUT_DIM + tx * 4]) = v;
        }
    }
}

// ---------------------------------------------------------------------------
// K2: per-node attention scalars s[n], d[n]. One warp per node.
// ---------------------------------------------------------------------------
__global__ __launch_bounds__(256) void sd_kernel(const float* __restrict__ attn_w) {
    int n    = (blockIdx.x * blockDim.x + threadIdx.x) >> 5;
    int lane = threadIdx.x & 31;
    if (n >= N_NODES) return;

    float z0 = g_z[(size_t)n * OUT_DIM + lane];
    float z1 = g_z[(size_t)n * OUT_DIM + 32 + lane];
    float s = z0 * attn_w[lane]      + z1 * attn_w[lane + 32];
    float d = z0 * attn_w[64 + lane] + z1 * attn_w[96 + lane];
#pragma unroll
    for (int o = 16; o > 0; o >>= 1) {
        s += __shfl_xor_sync(0xffffffffu, s, o);
        d += __shfl_xor_sync(0xffffffffu, d, o);
    }
    if (lane == 0) { g_s[n] = s; g_d[n] = d; }
}

// ---------------------------------------------------------------------------
// K3: segment boundaries via binary search (dst is sorted ascending).
// g_rs[n] = first edge index with dst >= n.
// ---------------------------------------------------------------------------
__global__ __launch_bounds__(256) void rowstart_kernel(const int* __restrict__ dst) {
    int n = blockIdx.x * blockDim.x + threadIdx.x;
    if (n > N_NODES) return;
    if (n == N_NODES) { g_rs[N_NODES] = N_EDGES; return; }
    int lo = 0, hi = N_EDGES;
    while (lo < hi) {
        int mid = (lo + hi) >> 1;
        if (dst[mid] < n) lo = mid + 1; else hi = mid;
    }
    g_rs[n] = lo;
}

// ---------------------------------------------------------------------------
// K4: fused edge softmax + aggregation. One warp per destination node.
// Pass 1 (lane-parallel over edges): e_i = lrelu(s[src_i] + d[n]); warp max.
// Pass 2 (serial over edges, lanes = output columns):
//   w_i = exp(e_i - m); num[col] += w_i * z[src_i][col]; den += w_i.
// out[n] = num / den. No atomics anywhere.
// ---------------------------------------------------------------------------
__global__ __launch_bounds__(256) void edge_agg_kernel(const int* __restrict__ src,
                                                       float* __restrict__ out) {
    int n    = (blockIdx.x * blockDim.x + threadIdx.x) >> 5;
    int lane = threadIdx.x & 31;
    if (n >= N_NODES) return;

    int beg = g_rs[n], end = g_rs[n + 1];
    float dn = g_d[n];

    // pass 1: segment max
    float m = -INFINITY;
    for (int i = beg + lane; i < end; i += 32) {
        float e = g_s[src[i]] + dn;
        e = (e > 0.f) ? e : NEG_SLOPE * e;
        m = fmaxf(m, e);
    }
#pragma unroll
    for (int o = 16; o > 0; o >>= 1)
        m = fmaxf(m, __shfl_xor_sync(0xffffffffu, m, o));

    // pass 2: weighted aggregation; each lane owns 2 output columns
    float acc0 = 0.f, acc1 = 0.f, den = 0.f;
    for (int i = beg; i < end; i++) {
        int sj = src[i];
        float e = g_s[sj] + dn;
        e = (e > 0.f) ? e : NEG_SLOPE * e;
        float w = __expf(e - m);
        const float* zr = g_z + (size_t)sj * OUT_DIM;
        acc0 += w * zr[lane];
        acc1 += w * zr[lane + 32];
        den  += w;
    }

    float inv = (end > beg) ? 1.f / den : 0.f;
    out[(size_t)n * OUT_DIM + lane]      = acc0 * inv;
    out[(size_t)n * OUT_DIM + lane + 32] = acc1 * inv;
}

// ---------------------------------------------------------------------------
extern "C" void kernel_launch(void* const* d_in, const int* in_sizes, int n_in,
                              void* d_out, int out_size) {
    const float* h      = (const float*)d_in[0];
    const int*   src    = (const int*)d_in[1];
    const int*   dst    = (const int*)d_in[2];
    const float* fc_w   = (const float*)d_in[3];
    const float* attn_w = (const float*)d_in[4];
    float*       out    = (float*)d_out;

    (void)in_sizes; (void)n_in; (void)out_size;

    gemm_kernel<<<(N_NODES + BM - 1) / BM, 256>>>(h, fc_w);
    sd_kernel<<<(N_NODES * 32 + 255) / 256, 256>>>(attn_w);
    rowstart_kernel<<<(N_NODES + 1 + 255) / 256, 256>>>(dst);
    edge_agg_kernel<<<(N_NODES * 32 + 255) / 256, 256>>>(src, out);
}

// round 3
// speedup vs baseline: 1.7773x; 1.7773x over previous
#include <cuda_runtime.h>
#include <math.h>
#include <stdint.h>

#define N_NODES   50000
#define N_EDGES   800000
#define IN_DIM    128
#define OUT_DIM   64
#define NEG_SLOPE 0.01f

// ---------------- scratch (static device globals; no allocation) ------------
__device__ float g_z[N_NODES * OUT_DIM];   // z = h @ fc_w^T
__device__ float g_s[N_NODES];             // z[n] . a_src
__device__ float g_d[N_NODES];             // z[n] . a_dst
__device__ int   g_rs[N_NODES + 1];        // row_start per dst node (dst sorted)

__device__ __forceinline__ uint32_t f2tf32(float x) {
    uint32_t u;
    asm("cvt.rna.tf32.f32 %0, %1;" : "=r"(u) : "f"(x));
    return u;
}

// ---------------------------------------------------------------------------
// K1: z = h @ fc_w^T via tf32 mma.sync.m16n8k8, fused s/d epilogue.
// Block = 256 threads = 8 warps; each warp computes 16 nodes x 64 outs.
// B fragments (weights) pre-swizzled into smem once per block.
// ---------------------------------------------------------------------------
#define GEMM_BM 128   // nodes per block (8 warps * 16)

__global__ __launch_bounds__(256) void gemm_sd_kernel(const float* __restrict__ h,
                                                      const float* __restrict__ fw,
                                                      const float* __restrict__ attn_w) {
    // wfrag[nt][kt][lane][2]  (8 * 16 * 32 * 2 u32 = 32 KB)
    __shared__ uint32_t wfrag[8 * 16 * 32 * 2];
    __shared__ float a_srcs[OUT_DIM];
    __shared__ float a_dsts[OUT_DIM];

    const int t    = threadIdx.x;
    const int wid  = t >> 5;
    const int lane = t & 31;
    const int gid  = lane >> 2;  // 0..7
    const int tid  = lane & 3;   // 0..3

    // ---- build B fragments: warp `wid` owns n_tile = wid --------------------
    // b0 = W[k = kt*8 + tid][n = wid*8 + gid], b1 = same with k+4.
    // W[k][n] = fw[n*IN_DIM + k].
    {
        const int n = wid * 8 + gid;
#pragma unroll
        for (int kt = 0; kt < 16; kt++) {
            int k = kt * 8 + tid;
            uint32_t b0 = f2tf32(fw[n * IN_DIM + k]);
            uint32_t b1 = f2tf32(fw[n * IN_DIM + k + 4]);
            int base = ((wid * 16 + kt) * 32 + lane) * 2;
            wfrag[base]     = b0;
            wfrag[base + 1] = b1;
        }
    }
    if (t < OUT_DIM)            a_srcs[t]           = attn_w[t];
    else if (t < 2 * OUT_DIM)   a_dsts[t - OUT_DIM] = attn_w[t];
    __syncthreads();

    // ---- mma mainloop -------------------------------------------------------
    const int node0 = blockIdx.x * GEMM_BM + wid * 16;
    const int r0 = node0 + gid;
    const int r1 = r0 + 8;
    const bool v0 = (r0 < N_NODES);
    const bool v1 = (r1 < N_NODES);
    const float* hr0 = h + (size_t)r0 * IN_DIM;
    const float* hr1 = h + (size_t)r1 * IN_DIM;

    float acc[8][4];
#pragma unroll
    for (int nt = 0; nt < 8; nt++)
#pragma unroll
        for (int c = 0; c < 4; c++) acc[nt][c] = 0.f;

#pragma unroll
    for (int kt = 0; kt < 16; kt++) {
        const int k = kt * 8 + tid;
        uint32_t a0 = f2tf32(v0 ? hr0[k]     : 0.f);
        uint32_t a1 = f2tf32(v1 ? hr1[k]     : 0.f);
        uint32_t a2 = f2tf32(v0 ? hr0[k + 4] : 0.f);
        uint32_t a3 = f2tf32(v1 ? hr1[k + 4] : 0.f);
#pragma unroll
        for (int nt = 0; nt < 8; nt++) {
            int base = ((nt * 16 + kt) * 32 + lane) * 2;
            uint32_t b0 = wfrag[base];
            uint32_t b1 = wfrag[base + 1];
            asm volatile(
                "mma.sync.aligned.m16n8k8.row.col.f32.tf32.tf32.f32 "
                "{%0,%1,%2,%3}, {%4,%5,%6,%7}, {%8,%9}, {%0,%1,%2,%3};"
                : "+f"(acc[nt][0]), "+f"(acc[nt][1]),
                  "+f"(acc[nt][2]), "+f"(acc[nt][3])
                : "r"(a0), "r"(a1), "r"(a2), "r"(a3), "r"(b0), "r"(b1));
        }
    }

    // ---- epilogue: store z + fused s/d --------------------------------------
    // c0:(r0, nt*8+tid*2) c1:(r0, +1) c2:(r1, tid*2) c3:(r1, +1)
    float s0 = 0.f, d0 = 0.f, s1 = 0.f, d1 = 0.f;
#pragma unroll
    for (int nt = 0; nt < 8; nt++) {
        int col = nt * 8 + tid * 2;
        if (v0) *((float2*)&g_z[(size_t)r0 * OUT_DIM + col]) =
                    make_float2(acc[nt][0], acc[nt][1]);
        if (v1) *((float2*)&g_z[(size_t)r1 * OUT_DIM + col]) =
                    make_float2(acc[nt][2], acc[nt][3]);
        float as0 = a_srcs[col], as1 = a_srcs[col + 1];
        float ad0 = a_dsts[col], ad1 = a_dsts[col + 1];
        s0 += acc[nt][0] * as0 + acc[nt][1] * as1;
        d0 += acc[nt][0] * ad0 + acc[nt][1] * ad1;
        s1 += acc[nt][2] * as0 + acc[nt][3] * as1;
        d1 += acc[nt][2] * ad0 + acc[nt][3] * ad1;
    }
    // reduce over the 4-lane quad (tid)
#pragma unroll
    for (int o = 1; o <= 2; o <<= 1) {
        s0 += __shfl_xor_sync(0xffffffffu, s0, o);
        d0 += __shfl_xor_sync(0xffffffffu, d0, o);
        s1 += __shfl_xor_sync(0xffffffffu, s1, o);
        d1 += __shfl_xor_sync(0xffffffffu, d1, o);
    }
    if (tid == 0) {
        if (v0) { g_s[r0] = s0; g_d[r0] = d0; }
        if (v1) { g_s[r1] = s1; g_d[r1] = d1; }
    }
}

// ---------------------------------------------------------------------------
// K3: segment boundaries via binary search (dst sorted ascending).
// ---------------------------------------------------------------------------
__global__ __launch_bounds__(256) void rowstart_kernel(const int* __restrict__ dst) {
    int n = blockIdx.x * blockDim.x + threadIdx.x;
    if (n > N_NODES) return;
    if (n == N_NODES) { g_rs[N_NODES] = N_EDGES; return; }
    int lo = 0, hi = N_EDGES;
    while (lo < hi) {
        int mid = (lo + hi) >> 1;
        if (dst[mid] < n) lo = mid + 1; else hi = mid;
    }
    g_rs[n] = lo;
}

// ---------------------------------------------------------------------------
// K4: fused edge softmax + aggregation, one warp per dst node.
// Chunked online softmax: per 64-edge chunk, lane-parallel e/exp with smem
// cache; serial accumulation reads cached w + src and float2 z rows.
// ---------------------------------------------------------------------------
#define CHUNK 64

__global__ __launch_bounds__(256) void edge_agg_kernel(const int* __restrict__ src,
                                                       float* __restrict__ out) {
    __shared__ float ebuf[8][CHUNK];
    __shared__ int   sbuf[8][CHUNK];

    const int n    = (blockIdx.x * blockDim.x + threadIdx.x) >> 5;
    const int wid  = (threadIdx.x >> 5);
    const int lane = threadIdx.x & 31;
    if (n >= N_NODES) return;

    const int beg = g_rs[n], end = g_rs[n + 1];
    const float dn = g_d[n];
    const float2* zz = (const float2*)g_z;

    float m_run = -INFINITY;
    float acc0 = 0.f, acc1 = 0.f, den = 0.f;

    for (int cbeg = beg; cbeg < end; cbeg += CHUNK) {
        const int cnt = min(CHUNK, end - cbeg);

        // lane-parallel: e_i, cache src + e
        float lmax = -INFINITY;
        for (int j = lane; j < cnt; j += 32) {
            int sj = src[cbeg + j];
            sbuf[wid][j] = sj;
            float e = g_s[sj] + dn;
            e = (e > 0.f) ? e : NEG_SLOPE * e;
            ebuf[wid][j] = e;
            lmax = fmaxf(lmax, e);
        }
#pragma unroll
        for (int o = 16; o > 0; o >>= 1)
            lmax = fmaxf(lmax, __shfl_xor_sync(0xffffffffu, lmax, o));

        const float m_new = fmaxf(m_run, lmax);
        const float sc = __expf(m_run - m_new);   // -inf first time -> 0
        acc0 *= sc; acc1 *= sc; den *= sc;

        // lane-parallel: w = exp(e - m), den partial
        float wsum = 0.f;
        for (int j = lane; j < cnt; j += 32) {
            float wv = __expf(ebuf[wid][j] - m_new);
            ebuf[wid][j] = wv;
            wsum += wv;
        }
#pragma unroll
        for (int o = 16; o > 0; o >>= 1)
            wsum += __shfl_xor_sync(0xffffffffu, wsum, o);
        den += wsum;
        __syncwarp();

        // serial over chunk edges: lanes own cols 2*lane, 2*lane+1
        int j = 0;
        for (; j + 2 <= cnt; j += 2) {
            float w0 = ebuf[wid][j], w1 = ebuf[wid][j + 1];
            int s0 = sbuf[wid][j],  s1 = sbuf[wid][j + 1];
            float2 za = zz[(size_t)s0 * 32 + lane];
            float2 zb = zz[(size_t)s1 * 32 + lane];
            acc0 += w0 * za.x + w1 * zb.x;
            acc1 += w0 * za.y + w1 * zb.y;
        }
        if (j < cnt) {
            float w0 = ebuf[wid][j];
            int s0 = sbuf[wid][j];
            float2 za = zz[(size_t)s0 * 32 + lane];
            acc0 += w0 * za.x;
            acc1 += w0 * za.y;
        }
        __syncwarp();
        m_run = m_new;
    }

    const float inv = (end > beg) ? 1.f / den : 0.f;
    ((float2*)out)[(size_t)n * 32 + lane] = make_float2(acc0 * inv, acc1 * inv);
}

// ---------------------------------------------------------------------------
extern "C" void kernel_launch(void* const* d_in, const int* in_sizes, int n_in,
                              void* d_out, int out_size) {
    const float* h      = (const float*)d_in[0];
    const int*   src    = (const int*)d_in[1];
    const int*   dst    = (const int*)d_in[2];
    const float* fc_w   = (const float*)d_in[3];
    const float* attn_w = (const float*)d_in[4];
    float*       out    = (float*)d_out;

    (void)in_sizes; (void)n_in; (void)out_size;

    rowstart_kernel<<<(N_NODES + 1 + 255) / 256, 256>>>(dst);
    gemm_sd_kernel<<<(N_NODES + GEMM_BM - 1) / GEMM_BM, 256>>>(h, fc_w, attn_w);
    edge_agg_kernel<<<(N_NODES * 32 + 255) / 256, 256>>>(src, out);
}

// round 4
// speedup vs baseline: 1.9087x; 1.0739x over previous
#include <cuda_runtime.h>
#include <math.h>
#include <stdint.h>

#define N_NODES   50000
#define N_EDGES   800000
#define IN_DIM    128
#define OUT_DIM   64
#define NEG_SLOPE 0.01f

// ---------------- scratch (static device globals; no allocation) ------------
__device__ float g_z[N_NODES * OUT_DIM];   // z = h @ fc_w^T
__device__ float g_s[N_NODES];             // z[n] . a_src
__device__ float g_d[N_NODES];             // z[n] . a_dst
__device__ int   g_rs[N_NODES + 1];        // row_start per dst node (dst sorted)

__device__ __forceinline__ uint32_t f2tf32(float x) {
    uint32_t u;
    asm("cvt.rna.tf32.f32 %0, %1;" : "=r"(u) : "f"(x));
    return u;
}

// ---------------------------------------------------------------------------
// K1: z = h @ fc_w^T via tf32 mma.sync.m16n8k8, fused s/d epilogue.
// Block = 256 threads = 8 warps; each warp computes 16 nodes x 64 outs.
// ---------------------------------------------------------------------------
#define GEMM_BM 128   // nodes per block (8 warps * 16)

__global__ __launch_bounds__(256) void gemm_sd_kernel(const float* __restrict__ h,
                                                      const float* __restrict__ fw,
                                                      const float* __restrict__ attn_w) {
    __shared__ uint32_t wfrag[8 * 16 * 32 * 2];   // 32 KB: B fragments
    __shared__ float a_srcs[OUT_DIM];
    __shared__ float a_dsts[OUT_DIM];

    const int t    = threadIdx.x;
    const int wid  = t >> 5;
    const int lane = t & 31;
    const int gid  = lane >> 2;  // 0..7
    const int tid  = lane & 3;   // 0..3

    // build B fragments: warp `wid` owns n_tile = wid
    {
        const int n = wid * 8 + gid;
#pragma unroll
        for (int kt = 0; kt < 16; kt++) {
            int k = kt * 8 + tid;
            uint32_t b0 = f2tf32(fw[n * IN_DIM + k]);
            uint32_t b1 = f2tf32(fw[n * IN_DIM + k + 4]);
            int base = ((wid * 16 + kt) * 32 + lane) * 2;
            wfrag[base]     = b0;
            wfrag[base + 1] = b1;
        }
    }
    if (t < OUT_DIM)            a_srcs[t]           = attn_w[t];
    else if (t < 2 * OUT_DIM)   a_dsts[t - OUT_DIM] = attn_w[t];
    __syncthreads();

    const int node0 = blockIdx.x * GEMM_BM + wid * 16;
    const int r0 = node0 + gid;
    const int r1 = r0 + 8;
    const bool v0 = (r0 < N_NODES);
    const bool v1 = (r1 < N_NODES);
    const float* hr0 = h + (size_t)r0 * IN_DIM;
    const float* hr1 = h + (size_t)r1 * IN_DIM;

    float acc[8][4];
#pragma unroll
    for (int nt = 0; nt < 8; nt++)
#pragma unroll
        for (int c = 0; c < 4; c++) acc[nt][c] = 0.f;

#pragma unroll
    for (int kt = 0; kt < 16; kt++) {
        const int k = kt * 8 + tid;
        uint32_t a0 = f2tf32(v0 ? hr0[k]     : 0.f);
        uint32_t a1 = f2tf32(v1 ? hr1[k]     : 0.f);
        uint32_t a2 = f2tf32(v0 ? hr0[k + 4] : 0.f);
        uint32_t a3 = f2tf32(v1 ? hr1[k + 4] : 0.f);
#pragma unroll
        for (int nt = 0; nt < 8; nt++) {
            int base = ((nt * 16 + kt) * 32 + lane) * 2;
            uint32_t b0 = wfrag[base];
            uint32_t b1 = wfrag[base + 1];
            asm volatile(
                "mma.sync.aligned.m16n8k8.row.col.f32.tf32.tf32.f32 "
                "{%0,%1,%2,%3}, {%4,%5,%6,%7}, {%8,%9}, {%0,%1,%2,%3};"
                : "+f"(acc[nt][0]), "+f"(acc[nt][1]),
                  "+f"(acc[nt][2]), "+f"(acc[nt][3])
                : "r"(a0), "r"(a1), "r"(a2), "r"(a3), "r"(b0), "r"(b1));
        }
    }

    // epilogue: store z + fused s/d
    float s0 = 0.f, d0 = 0.f, s1 = 0.f, d1 = 0.f;
#pragma unroll
    for (int nt = 0; nt < 8; nt++) {
        int col = nt * 8 + tid * 2;
        if (v0) *((float2*)&g_z[(size_t)r0 * OUT_DIM + col]) =
                    make_float2(acc[nt][0], acc[nt][1]);
        if (v1) *((float2*)&g_z[(size_t)r1 * OUT_DIM + col]) =
                    make_float2(acc[nt][2], acc[nt][3]);
        float as0 = a_srcs[col], as1 = a_srcs[col + 1];
        float ad0 = a_dsts[col], ad1 = a_dsts[col + 1];
        s0 += acc[nt][0] * as0 + acc[nt][1] * as1;
        d0 += acc[nt][0] * ad0 + acc[nt][1] * ad1;
        s1 += acc[nt][2] * as0 + acc[nt][3] * as1;
        d1 += acc[nt][2] * ad0 + acc[nt][3] * ad1;
    }
#pragma unroll
    for (int o = 1; o <= 2; o <<= 1) {
        s0 += __shfl_xor_sync(0xffffffffu, s0, o);
        d0 += __shfl_xor_sync(0xffffffffu, d0, o);
        s1 += __shfl_xor_sync(0xffffffffu, s1, o);
        d1 += __shfl_xor_sync(0xffffffffu, d1, o);
    }
    if (tid == 0) {
        if (v0) { g_s[r0] = s0; g_d[r0] = d0; }
        if (v1) { g_s[r1] = s1; g_d[r1] = d1; }
    }
}

// ---------------------------------------------------------------------------
// K3: segment boundaries via edge-difference scan (dst sorted ascending).
// Thread i: writes g_rs[n] = i for all n in (dst[i-1], dst[i]].
// Thread 0 fills [0, dst[0]]; a tail thread fills (dst[last], N_NODES].
// Coalesced streaming reads, no dependent-load chains.
// ---------------------------------------------------------------------------
__global__ __launch_bounds__(256) void rowstart_kernel(const int* __restrict__ dst) {
    int i = blockIdx.x * blockDim.x + threadIdx.x;
    if (i >= N_EDGES) return;

    int d1 = dst[i];
    if (i == 0) {
        for (int n = 0; n <= d1; n++) g_rs[n] = 0;
    } else {
        int d0 = dst[i - 1];
        for (int n = d0 + 1; n <= d1; n++) g_rs[n] = i;
    }
    if (i == N_EDGES - 1) {
        for (int n = d1 + 1; n <= N_NODES; n++) g_rs[n] = N_EDGES;
    }
}

// ---------------------------------------------------------------------------
// K4: fused edge softmax + aggregation, one warp per dst node.
// Chunked online softmax; serial aggregation unrolled x4 for MLP.
// ---------------------------------------------------------------------------
#define CHUNK 64

__global__ __launch_bounds__(256) void edge_agg_kernel(const int* __restrict__ src,
                                                       float* __restrict__ out) {
    __shared__ float ebuf[8][CHUNK];
    __shared__ int   sbuf[8][CHUNK];

    const int n    = (blockIdx.x * blockDim.x + threadIdx.x) >> 5;
    const int wid  = (threadIdx.x >> 5);
    const int lane = threadIdx.x & 31;
    if (n >= N_NODES) return;

    const int beg = g_rs[n], end = g_rs[n + 1];
    const float dn = g_d[n];
    const float2* zz = (const float2*)g_z;

    float m_run = -INFINITY;
    float acc0 = 0.f, acc1 = 0.f, den = 0.f;

    for (int cbeg = beg; cbeg < end; cbeg += CHUNK) {
        const int cnt = min(CHUNK, end - cbeg);

        // lane-parallel: e_i, cache src + e
        float lmax = -INFINITY;
        for (int j = lane; j < cnt; j += 32) {
            int sj = src[cbeg + j];
            sbuf[wid][j] = sj;
            float e = g_s[sj] + dn;
            e = (e > 0.f) ? e : NEG_SLOPE * e;
            ebuf[wid][j] = e;
            lmax = fmaxf(lmax, e);
        }
#pragma unroll
        for (int o = 16; o > 0; o >>= 1)
            lmax = fmaxf(lmax, __shfl_xor_sync(0xffffffffu, lmax, o));

        const float m_new = fmaxf(m_run, lmax);
        const float sc = __expf(m_run - m_new);
        acc0 *= sc; acc1 *= sc; den *= sc;

        // lane-parallel: w = exp(e - m), partial den
        float wsum = 0.f;
        for (int j = lane; j < cnt; j += 32) {
            float wv = __expf(ebuf[wid][j] - m_new);
            ebuf[wid][j] = wv;
            wsum += wv;
        }
#pragma unroll
        for (int o = 16; o > 0; o >>= 1)
            wsum += __shfl_xor_sync(0xffffffffu, wsum, o);
        den += wsum;
        __syncwarp();

        // serial over chunk edges, x4 unrolled (8 LDGs in flight)
        int j = 0;
        for (; j + 4 <= cnt; j += 4) {
            float w0 = ebuf[wid][j],     w1 = ebuf[wid][j + 1];
            float w2 = ebuf[wid][j + 2], w3 = ebuf[wid][j + 3];
            int s0 = sbuf[wid][j],       s1 = sbuf[wid][j + 1];
            int s2 = sbuf[wid][j + 2],   s3 = sbuf[wid][j + 3];
            float2 za = zz[(size_t)s0 * 32 + lane];
            float2 zb = zz[(size_t)s1 * 32 + lane];
            float2 zc = zz[(size_t)s2 * 32 + lane];
            float2 zd = zz[(size_t)s3 * 32 + lane];
            acc0 += w0 * za.x + w1 * zb.x + w2 * zc.x + w3 * zd.x;
            acc1 += w0 * za.y + w1 * zb.y + w2 * zc.y + w3 * zd.y;
        }
        for (; j < cnt; j++) {
            float w0 = ebuf[wid][j];
            int s0 = sbuf[wid][j];
            float2 za = zz[(size_t)s0 * 32 + lane];
            acc0 += w0 * za.x;
            acc1 += w0 * za.y;
        }
        __syncwarp();
        m_run = m_new;
    }

    const float inv = (end > beg) ? 1.f / den : 0.f;
    ((float2*)out)[(size_t)n * 32 + lane] = make_float2(acc0 * inv, acc1 * inv);
}

// ---------------------------------------------------------------------------
extern "C" void kernel_launch(void* const* d_in, const int* in_sizes, int n_in,
                              void* d_out, int out_size) {
    const float* h      = (const float*)d_in[0];
    const int*   src    = (const int*)d_in[1];
    const int*   dst    = (const int*)d_in[2];
    const float* fc_w   = (const float*)d_in[3];
    const float* attn_w = (const float*)d_in[4];
    float*       out    = (float*)d_out;

    (void)in_sizes; (void)n_in; (void)out_size;

    rowstart_kernel<<<(N_EDGES + 255) / 256, 256>>>(dst);
    gemm_sd_kernel<<<(N_NODES + GEMM_BM - 1) / GEMM_BM, 256>>>(h, fc_w, attn_w);
    edge_agg_kernel<<<(N_NODES * 32 + 255) / 256, 256>>>(src, out);
}